// round 3
// baseline (speedup 1.0000x reference)
#include <cuda_runtime.h>

#define BQ     2048
#define INDIM  512
#define OUTDIM 512
#define NEXP   64

#define BM 32
#define BN 128
#define BK 64
#define NTHREADS 256

// Scratch (no allocation allowed): per-expert counts + sample lists.
__device__ int g_count[NEXP];
__device__ int g_list[NEXP * BQ];

__global__ void zero_counts_kernel() {
    if (threadIdx.x < NEXP) g_count[threadIdx.x] = 0;
}

// ids buffer is int32 (JAX default config downcasts jnp.int64 -> int32).
__global__ void build_lists_kernel(const int* __restrict__ ids) {
    int i = blockIdx.x * blockDim.x + threadIdx.x;
    if (i < BQ) {
        int e = ids[i];
        if (e >= 0 && e < NEXP) {                // defensive: never write OOB
            int pos = atomicAdd(&g_count[e], 1);
            if (pos < BQ) g_list[e * BQ + pos] = i;
        }
    }
}

__device__ __forceinline__ unsigned long long dup_f32(float v) {
    unsigned long long r;
    unsigned int u = __float_as_uint(v);
    asm("mov.b64 %0, {%1, %1};" : "=l"(r) : "r"(u));
    return r;
}

__device__ __forceinline__ void fma2(unsigned long long& d,
                                     unsigned long long a,
                                     unsigned long long b) {
    asm("fma.rn.f32x2 %0, %1, %2, %0;" : "+l"(d) : "l"(a), "l"(b));
}

// Grid: (OUTDIM/BN = 4, NEXP = 64). Block: 256 threads.
// Block (tile, e): for each chunk of up to BM samples of expert e,
// compute [chunk, BN] = x[chunk, :] * W[e, tile*BN:+BN, :]^T
__global__ __launch_bounds__(NTHREADS, 2) void gemm_kernel(
    const float* __restrict__ x,
    const float* __restrict__ w,
    float* __restrict__ out)
{
    __shared__ float xs[BK][BM + 4];   // [64][36], +4 keeps float4 alignment
    __shared__ float ws[BK][BN];       // [64][128] = 32 KB
    __shared__ int sidx[BM];

    const int e    = blockIdx.y;
    const int tile = blockIdx.x;
    const int n    = g_count[e];
    if (n == 0) return;

    const int tid = threadIdx.x;
    const int r = tid >> 5;   // 0..7  -> samples r*4 .. r*4+3
    const int c = tid & 31;   // 0..31 -> outs    c*4 .. c*4+3

    const int* ls = g_list + e * BQ;
    const float* wbase = w + ((size_t)e * OUTDIM + (size_t)tile * BN) * INDIM;

    for (int m0 = 0; m0 < n; m0 += BM) {
        __syncthreads();   // previous chunk's stores (which read sidx) are done
        if (tid < BM) {
            int m = m0 + tid;
            sidx[tid] = ls[m < n ? m : 0];   // clamp: duplicate work, masked at store
        }

        unsigned long long acc[4][2];
        #pragma unroll
        for (int i = 0; i < 4; i++) { acc[i][0] = 0ULL; acc[i][1] = 0ULL; }

        for (int k0 = 0; k0 < INDIM; k0 += BK) {
            __syncthreads();   // sidx visible / previous compute done

            // ---- load x chunk: 32 rows x 64 cols, transposed into xs[k][m]
            #pragma unroll
            for (int q = 0; q < 2; q++) {
                int lin = q * NTHREADS + tid;          // 0..511
                int row = lin >> 4;                    // 0..31
                int c4  = lin & 15;                    // 0..15
                const float4 v = *(const float4*)(x + (size_t)sidx[row] * INDIM + k0 + c4 * 4);
                int k = c4 * 4;
                xs[k + 0][row] = v.x;
                xs[k + 1][row] = v.y;
                xs[k + 2][row] = v.z;
                xs[k + 3][row] = v.w;
            }

            // ---- load weight slab: 128 rows x 64 cols, transposed into ws[k][n]
            {
                int nn   = tid >> 1;                   // 0..127
                int half = tid & 1;
                const float* wr = wbase + (size_t)nn * INDIM + k0 + half * 32;
                #pragma unroll
                for (int q = 0; q < 8; q++) {
                    const float4 v = *(const float4*)(wr + q * 4);
                    int k = half * 32 + q * 4;
                    ws[k + 0][nn] = v.x;
                    ws[k + 1][nn] = v.y;
                    ws[k + 2][nn] = v.z;
                    ws[k + 3][nn] = v.w;
                }
            }
            __syncthreads();

            // ---- compute: per kk, 2x LDS.128 + 4 packs + 8 fma.rn.f32x2
            #pragma unroll 8
            for (int kk = 0; kk < BK; kk++) {
                const float4 av = *(const float4*)&xs[kk][r * 4];          // warp-broadcast
                const ulonglong2 bv = *(const ulonglong2*)&ws[kk][c * 4];  // conflict-free

                unsigned long long a0 = dup_f32(av.x);
                unsigned long long a1 = dup_f32(av.y);
                unsigned long long a2 = dup_f32(av.z);
                unsigned long long a3 = dup_f32(av.w);

                fma2(acc[0][0], a0, bv.x); fma2(acc[0][1], a0, bv.y);
                fma2(acc[1][0], a1, bv.x); fma2(acc[1][1], a1, bv.y);
                fma2(acc[2][0], a2, bv.x); fma2(acc[2][1], a2, bv.y);
                fma2(acc[3][0], a3, bv.x); fma2(acc[3][1], a3, bv.y);
            }
        }

        // ---- store: rows m0 + r*4 + i (masked), cols tile*BN + c*4 .. +3
        #pragma unroll
        for (int i = 0; i < 4; i++) {
            int m = m0 + r * 4 + i;
            if (m < n) {
                int s = sidx[r * 4 + i];
                float4 o;
                o.x = __uint_as_float((unsigned int)(acc[i][0]));
                o.y = __uint_as_float((unsigned int)(acc[i][0] >> 32));
                o.z = __uint_as_float((unsigned int)(acc[i][1]));
                o.w = __uint_as_float((unsigned int)(acc[i][1] >> 32));
                *(float4*)(out + (size_t)s * OUTDIM + (size_t)tile * BN + c * 4) = o;
            }
        }
    }
}

extern "C" void kernel_launch(void* const* d_in, const int* in_sizes, int n_in,
                              void* d_out, int out_size) {
    // Identify inputs by element count (robust to metadata ordering):
    // x: 2048*512 = 1048576, ids: 2048, weight: 64*512*512 = 16777216
    const float* x = nullptr;
    const int* ids = nullptr;
    const float* w = nullptr;
    for (int i = 0; i < n_in; i++) {
        if (in_sizes[i] == BQ * INDIM)                 x   = (const float*)d_in[i];
        else if (in_sizes[i] == BQ)                    ids = (const int*)d_in[i];
        else if (in_sizes[i] == NEXP * OUTDIM * INDIM) w   = (const float*)d_in[i];
    }
    float* out = (float*)d_out;

    zero_counts_kernel<<<1, 64>>>();
    build_lists_kernel<<<(BQ + 255) / 256, 256>>>(ids);
    gemm_kernel<<<dim3(OUTDIM / BN, NEXP), NTHREADS>>>(x, w, out);
}

// round 6
// speedup vs baseline: 1.1431x; 1.1431x over previous
#include <cuda_runtime.h>

#define BQ     2048
#define IND    512
#define OUTD   512
#define NEXP   64

#define BM     16
#define BN     256
#define BK     32
#define NT     64          // threads per gemm CTA (2 warps)
#define NTILES (OUTD / BN) // 2
#define GRID_GEMM 384      // worst-case item count: sum ceil(n_e/16)*2 <= 384
#define MAXITEMS 512

// Global scratch (static __device__ arrays: no allocation).
__device__ int g_count[NEXP];
__device__ int g_list[NEXP * BQ];
__device__ int g_items[MAXITEMS];
__device__ int g_nitems;

// ---------------- prep: counts, per-expert lists, work-item list ----------------
__global__ void prep_kernel(const int* __restrict__ ids) {
    __shared__ int sc[NEXP];
    int t = threadIdx.x;
    if (t < NEXP) sc[t] = 0;
    __syncthreads();
    for (int i = t; i < BQ; i += blockDim.x) {
        int e = ids[i];
        if ((unsigned)e < NEXP) {
            int p = atomicAdd(&sc[e], 1);
            g_list[e * BQ + p] = i;
        }
    }
    __syncthreads();
    if (t < NEXP) g_count[t] = sc[t];
    if (t == 0) {
        int ni = 0;
        for (int e = 0; e < NEXP; e++) {
            int n = sc[e];
            for (int c = 0; c * BM < n && ni < MAXITEMS - NTILES; c++)
                for (int tl = 0; tl < NTILES; tl++)
                    g_items[ni++] = (e << 16) | (c << 1) | tl;
        }
        g_nitems = ni;
    }
}

// ---------------- packed fp32 helpers ----------------
__device__ __forceinline__ unsigned long long dup_f32(float v) {
    unsigned long long r;
    unsigned int u = __float_as_uint(v);
    asm("mov.b64 %0, {%1, %1};" : "=l"(r) : "r"(u));
    return r;
}
__device__ __forceinline__ void fma2(unsigned long long& d,
                                     unsigned long long a,
                                     unsigned long long b) {
    asm("fma.rn.f32x2 %0, %1, %2, %0;" : "+l"(d) : "l"(a), "l"(b));
}

// ---------------- grouped GEMM: one uniform-cost item per CTA ----------------
// Item = (expert, chunk of 16 samples, N-tile of 256 outs). Every item runs the
// full K=512 loop, so items are equal cost and a static map is balanced.
// CTA: 64 threads, each owns an 8x8 output micro-tile (8x4 packed f32x2).
__global__ __launch_bounds__(NT) void gemm_kernel(
    const float* __restrict__ x,
    const float* __restrict__ w,
    float* __restrict__ out)
{
    __shared__ float ws[BK][BN];                 // 32 KB, [k][n]
    __shared__ unsigned long long xs[BK][BM];    // 4 KB, dup-packed x, [k][m]
    __shared__ int sidx[BM];

    const int it = blockIdx.x;
    if (it >= g_nitems) return;

    const int t    = threadIdx.x;
    const int lane = t & 31;
    const int wrp  = t >> 5;
    const int mg   = lane & 1;          // 0..1 : rows mg*8..mg*8+7
    const int cg   = lane >> 1;         // 0..15: cols wrp*128 + cg*8 .. +7
    const int colw = wrp * 128 + cg * 8;

    const int pk   = g_items[it];
    const int e    = pk >> 16;
    const int tile = pk & 1;
    const int m0   = ((pk >> 1) & 0x7fff) * BM;
    const int n    = g_count[e];
    const int* ls  = g_list + e * BQ;

    if (t < BM) { int m = m0 + t; sidx[t] = ls[m < n ? m : 0]; }

    const float* wb = w + ((size_t)e * OUTD + (size_t)tile * BN) * IND;

    unsigned long long acc[8][4];
    #pragma unroll
    for (int r = 0; r < 8; r++)
        #pragma unroll
        for (int c = 0; c < 4; c++) acc[r][c] = 0ULL;

    for (int k0 = 0; k0 < IND; k0 += BK) {
        __syncthreads();   // sidx ready (first iter) / previous compute done

        // ---- fill ws: BN rows x BK cols of W, transposed to [k][n].
        {
            const int qh = (t & 1) * 16;
            #pragma unroll
            for (int j = 0; j < 8; j++) {
                int nr = (t >> 1) + 32 * j;
                const float4* src = (const float4*)(wb + (size_t)nr * IND + k0 + qh);
                #pragma unroll
                for (int qq = 0; qq < 4; qq++) {
                    float4 v = src[qq];
                    int k = qh + qq * 4;
                    ws[k + 0][nr] = v.x;
                    ws[k + 1][nr] = v.y;
                    ws[k + 2][nr] = v.z;
                    ws[k + 3][nr] = v.w;
                }
            }
        }
        // ---- fill xs (dup-packed): 16 samples x 32 k = 128 float4, 2/thread
        #pragma unroll
        for (int s = 0; s < 2; s++) {
            int f = t + NT * s;          // 0..127
            int m = f >> 3;              // 0..15
            int q = f & 7;               // 0..7
            float4 v = *(const float4*)(x + (size_t)sidx[m] * IND + k0 + q * 4);
            xs[q * 4 + 0][m] = dup_f32(v.x);
            xs[q * 4 + 1][m] = dup_f32(v.y);
            xs[q * 4 + 2][m] = dup_f32(v.z);
            xs[q * 4 + 3][m] = dup_f32(v.w);
        }
        __syncthreads();

        // ---- compute
        #pragma unroll 4
        for (int kk = 0; kk < BK; kk++) {
            const ulonglong2* xr = (const ulonglong2*)&xs[kk][mg * 8];
            const ulonglong2* br = (const ulonglong2*)&ws[kk][colw];
            ulonglong2 a01 = xr[0];
            ulonglong2 a23 = xr[1];
            ulonglong2 a45 = xr[2];
            ulonglong2 a67 = xr[3];
            ulonglong2 b01 = br[0];
            ulonglong2 b23 = br[1];

            unsigned long long av[8] = {a01.x, a01.y, a23.x, a23.y,
                                        a45.x, a45.y, a67.x, a67.y};
            unsigned long long bv[4] = {b01.x, b01.y, b23.x, b23.y};
            #pragma unroll
            for (int r = 0; r < 8; r++)
                #pragma unroll
                for (int c = 0; c < 4; c++)
                    fma2(acc[r][c], av[r], bv[c]);
        }
    }

    // ---- store 8 rows x 8 cols (rows masked to n)
    #pragma unroll
    for (int r = 0; r < 8; r++) {
        int m = m0 + mg * 8 + r;
        if (m < n) {
            float* op = out + (size_t)sidx[mg * 8 + r] * OUTD + tile * BN + colw;
            float4 o0, o1;
            o0.x = __uint_as_float((unsigned)(acc[r][0]));
            o0.y = __uint_as_float((unsigned)(acc[r][0] >> 32));
            o0.z = __uint_as_float((unsigned)(acc[r][1]));
            o0.w = __uint_as_float((unsigned)(acc[r][1] >> 32));
            o1.x = __uint_as_float((unsigned)(acc[r][2]));
            o1.y = __uint_as_float((unsigned)(acc[r][2] >> 32));
            o1.z = __uint_as_float((unsigned)(acc[r][3]));
            o1.w = __uint_as_float((unsigned)(acc[r][3] >> 32));
            *(float4*)op       = o0;
            *(float4*)(op + 4) = o1;
        }
    }
}

extern "C" void kernel_launch(void* const* d_in, const int* in_sizes, int n_in,
                              void* d_out, int out_size) {
    const float* x = nullptr;
    const int* ids = nullptr;
    const float* w = nullptr;
    for (int i = 0; i < n_in; i++) {
        if (in_sizes[i] == BQ * IND)                x   = (const float*)d_in[i];
        else if (in_sizes[i] == BQ)                 ids = (const int*)d_in[i];
        else if (in_sizes[i] == NEXP * OUTD * IND)  w   = (const float*)d_in[i];
    }
    float* out = (float*)d_out;

    prep_kernel<<<1, 256>>>(ids);
    gemm_kernel<<<GRID_GEMM, NT>>>(x, w, out);
}